// round 6
// baseline (speedup 1.0000x reference)
#include <cuda_runtime.h>
#include <math.h>
#include <stdint.h>

#define KCODES 512
#define DIM 64
#define NROWS 262144
#define ROWS_PER_CTA 64
#define NBLOCKS (NROWS / ROWS_PER_CTA)   // 4096
#define TPB 128
#define MARGIN 1e-3f

#define SDP 516                          // s_dist row stride (words), conflict-padded
#define WCH 68                           // s_w code stride (words), conflict-padded
#define SW_WORDS (64 * WCH)              // 4352 words per W-chunk buffer
#define DIST_WORDS (ROWS_PER_CTA * SDP)  // 33024
#define DYN_WORDS (DIST_WORDS + 2 * SW_WORDS)
#define DYN_SMEM (DYN_WORDS * 4)         // 166912 B

// Scratch (no allocations allowed)
__device__ float  g_sw[KCODES];
__device__ int    g_counts[KCODES];
__device__ double g_partial[NBLOCKS];

__device__ __forceinline__ uint32_t smem_u32(const void* p) {
    uint32_t a;
    asm("{ .reg .u64 t; cvta.to.shared.u64 t, %1; cvt.u32.u64 %0, t; }" : "=r"(a) : "l"(p));
    return a;
}
__device__ __forceinline__ uint32_t to_tf32(float f) {
    uint32_t r;
    asm("cvt.rna.tf32.f32 %0, %1;" : "=r"(r) : "f"(f));
    return r;
}
__device__ __forceinline__ void mma1688(float& c0, float& c1, float& c2, float& c3,
                                        uint32_t a0, uint32_t a1, uint32_t a2, uint32_t a3,
                                        uint32_t b0, uint32_t b1) {
    asm volatile("mma.sync.aligned.m16n8k8.row.col.f32.tf32.tf32.f32 "
                 "{%0,%1,%2,%3}, {%4,%5,%6,%7}, {%8,%9}, {%0,%1,%2,%3};"
                 : "+f"(c0), "+f"(c1), "+f"(c2), "+f"(c3)
                 : "r"(a0), "r"(a1), "r"(a2), "r"(a3), "r"(b0), "r"(b1));
}
__device__ __forceinline__ void cpasync16(uint32_t saddr, const void* g) {
    asm volatile("cp.async.cg.shared.global [%0], [%1], 16;" :: "r"(saddr), "l"(g) : "memory");
}

// ---------------------------------------------------------------------------
// Kernel 1: per-code squared norms (EXACT association proven in R2) + hist zero
// ---------------------------------------------------------------------------
__global__ void vq_prep(const float* __restrict__ W) {
    int k = blockIdx.x * 64 + threadIdx.x;   // 8 x 64
    const float4* w = (const float4*)(W + (size_t)k * DIM);
    float s = 0.0f;
    #pragma unroll
    for (int g = 0; g < 16; ++g) {
        float4 v = w[g];
        s += v.x * v.x; s += v.y * v.y; s += v.z * v.z; s += v.w * v.w;
    }
    g_sw[k] = s;
    g_counts[k] = 0;
}

// ---------------------------------------------------------------------------
// Kernel 2: TF32 mma.sync scoring -> prune -> exact fp32 re-rank -> outputs
// Output layout: out[0]=loss | out[1..1+N*64)=q_st | out[1+N*64]=perp | idx
// ---------------------------------------------------------------------------
extern "C" __global__ void __launch_bounds__(TPB, 1)
vq_main(const float* __restrict__ X, const float* __restrict__ W,
        float* __restrict__ out) {
    extern __shared__ float dynsm[];
    float* s_dist = dynsm;                   // [64][516]
    float* s_w    = dynsm + DIST_WORDS;      // 2 x [64][68]
    __shared__ float  s_sw[KCODES];
    __shared__ double s_red[TPB];

    const int tid  = threadIdx.x;
    const int lane = tid & 31;
    const int warp = tid >> 5;
    const int g    = lane >> 2;      // row group 0..7
    const int tl   = lane & 3;       // k group 0..3
    const int rowBase = blockIdx.x * ROWS_PER_CTA;

    for (int i = tid; i < KCODES; i += TPB) s_sw[i] = g_sw[i];

    const uint32_t swbase = smem_u32(s_w);

    // prefetch W chunk 0 (64 codes x 64 f32) via cp.async
    {
        const float4* gsrc = (const float4*)W;
        for (int i = tid; i < 1024; i += TPB) {
            int code = i >> 4, d4 = i & 15;
            cpasync16(swbase + (uint32_t)(code * WCH + d4 * 4) * 4, gsrc + i);
        }
        asm volatile("cp.async.commit_group;" ::: "memory");
    }

    // A fragments: 16 rows x 64 dims per warp, tf32-converted, in registers
    uint32_t a[8][4];
    {
        const float* xr0 = X + (size_t)(rowBase + warp * 16 + g) * DIM;
        const float* xr8 = xr0 + 8 * DIM;
        #pragma unroll
        for (int s = 0; s < 8; ++s) {
            a[s][0] = to_tf32(xr0[8 * s + tl]);
            a[s][1] = to_tf32(xr8[8 * s + tl]);
            a[s][2] = to_tf32(xr0[8 * s + tl + 4]);
            a[s][3] = to_tf32(xr8[8 * s + tl + 4]);
        }
    }

    // ---- chunk loop: 8 chunks of 64 codes, double-buffered ----
    for (int c = 0; c < 8; ++c) {
        const int buf = c & 1;
        asm volatile("cp.async.wait_group 0;" ::: "memory");
        __syncthreads();
        if (c < 7) {
            const float4* gsrc = (const float4*)(W + (size_t)(c + 1) * 64 * DIM);
            uint32_t dstb = swbase + (uint32_t)((buf ^ 1) * SW_WORDS) * 4;
            for (int i = tid; i < 1024; i += TPB) {
                int code = i >> 4, d4 = i & 15;
                cpasync16(dstb + (uint32_t)(code * WCH + d4 * 4) * 4, gsrc + i);
            }
            asm volatile("cp.async.commit_group;" ::: "memory");
        }

        const float* wbuf = s_w + buf * SW_WORDS;
        float acc[8][4];
        #pragma unroll
        for (int t = 0; t < 8; ++t)
            acc[t][0] = acc[t][1] = acc[t][2] = acc[t][3] = 0.0f;

        #pragma unroll
        for (int s = 0; s < 8; ++s) {
            #pragma unroll
            for (int t = 0; t < 8; ++t) {
                // B[k][n]: code = t*8+g, dims 8s+tl, 8s+tl+4 (raw f32 -> HW tf32 trunc)
                uint32_t b0 = __float_as_uint(wbuf[(t * 8 + g) * WCH + 8 * s + tl]);
                uint32_t b1 = __float_as_uint(wbuf[(t * 8 + g) * WCH + 8 * s + tl + 4]);
                mma1688(acc[t][0], acc[t][1], acc[t][2], acc[t][3],
                        a[s][0], a[s][1], a[s][2], a[s][3], b0, b1);
            }
        }

        // r = sw_k - 2*dot -> s_dist
        const int drow = warp * 16 + g;
        #pragma unroll
        for (int t = 0; t < 8; ++t) {
            const int k0 = c * 64 + t * 8 + 2 * tl;
            float2 lo = make_float2(fmaf(acc[t][0], -2.0f, s_sw[k0]),
                                    fmaf(acc[t][1], -2.0f, s_sw[k0 + 1]));
            float2 hi = make_float2(fmaf(acc[t][2], -2.0f, s_sw[k0]),
                                    fmaf(acc[t][3], -2.0f, s_sw[k0 + 1]));
            *(float2*)&s_dist[(size_t)drow * SDP + k0]       = lo;
            *(float2*)&s_dist[(size_t)(drow + 8) * SDP + k0] = hi;
        }
    }
    __syncthreads();

    // ---- scan: 2 threads per row (halves of 256 codes each) ----
    const int row  = tid >> 1;
    const int half = tid & 1;
    const int rowG = rowBase + row;
    const float* dr = s_dist + (size_t)row * SDP + half * 256;

    float minr = __int_as_float(0x7f800000);
    for (int j = 0; j < 256; j += 4) {
        float4 v = *(const float4*)&dr[j];
        minr = fminf(minr, fminf(fminf(v.x, v.y), fminf(v.z, v.w)));
    }
    float om = __shfl_xor_sync(0xffffffffu, minr, 1);
    const float cutoff = fminf(minr, om) + MARGIN;

    int cnt = 0;
    int ck[8] = {0, 0, 0, 0, 0, 0, 0, 0};
    for (int j = 0; j < 256; j += 4) {
        float4 v = *(const float4*)&dr[j];
        #pragma unroll
        for (int e = 0; e < 4; ++e) {
            float rv = (e == 0) ? v.x : (e == 1) ? v.y : (e == 2) ? v.z : v.w;
            if (rv < cutoff) {
                if (cnt < 8) ck[cnt] = half * 256 + j + e;
                cnt++;
            }
        }
    }
    int ocnt = __shfl_xor_sync(0xffffffffu, cnt, 1);
    int ock[8];
    #pragma unroll
    for (int i = 0; i < 8; ++i) ock[i] = __shfl_xor_sync(0xffffffffu, ck[i], 1);
    const bool over = (cnt > 8) || (ocnt > 8);

    int bestIdx = 0;
    if (half == 0) {
        // exact comparator (R2 association, proven flip-free)
        float4 x[16];
        const float4* xp = (const float4*)(X + (size_t)rowG * DIM);
        #pragma unroll
        for (int gg = 0; gg < 16; ++gg) x[gg] = xp[gg];
        float sx = 0.0f;
        #pragma unroll
        for (int gg = 0; gg < 16; ++gg) {
            sx += x[gg].x * x[gg].x; sx += x[gg].y * x[gg].y;
            sx += x[gg].z * x[gg].z; sx += x[gg].w * x[gg].w;
        }
        float bestDist = __int_as_float(0x7f800000);

        #define EXACT_CHECK(kk) {                                              \
            const int k_ = (kk);                                               \
            const float4* wp = (const float4*)(W + (size_t)k_ * DIM);          \
            float dot = 0.0f;                                                  \
            _Pragma("unroll")                                                  \
            for (int gg = 0; gg < 16; ++gg) {                                  \
                float4 w4 = __ldg(wp + gg);                                    \
                dot += x[gg].x * w4.x; dot += x[gg].y * w4.y;                  \
                dot += x[gg].z * w4.z; dot += x[gg].w * w4.w;                  \
            }                                                                  \
            float tt = sx + s_sw[k_];                                          \
            float dist = tt - 2.0f * dot;                                      \
            if (dist < bestDist) { bestDist = dist; bestIdx = k_; }            \
        }

        if (over) {
            for (int k = 0; k < KCODES; ++k) EXACT_CHECK(k);
        } else {
            for (int i = 0; i < cnt; ++i)  EXACT_CHECK(ck[i]);   // half0: k<256, asc
            for (int i = 0; i < ocnt; ++i) EXACT_CHECK(ock[i]);  // half1: k>=256, asc
        }
        #undef EXACT_CHECK

        out[2 + (size_t)NROWS * DIM + rowG] = (float)bestIdx;
        atomicAdd(&g_counts[bestIdx], 1);
    }
    bestIdx = __shfl_sync(0xffffffffu, bestIdx, lane & ~1);

    // ---- q_st + loss: each half writes its 32 dims (scalar stores: 4B-aligned)
    double lsum = 0.0;
    {
        const float4* qp  = (const float4*)(W + (size_t)bestIdx * DIM + half * 32);
        const float4* xp2 = (const float4*)(X + (size_t)rowG * DIM + half * 32);
        float* op = out + 1 + (size_t)rowG * DIM + half * 32;
        #pragma unroll
        for (int gg = 0; gg < 8; ++gg) {
            float4 q4 = __ldg(qp + gg);
            float4 xv = xp2[gg];
            float e;
            e = q4.x - xv.x; op[4*gg + 0] = xv.x + e; lsum += (double)(e * e);
            e = q4.y - xv.y; op[4*gg + 1] = xv.y + e; lsum += (double)(e * e);
            e = q4.z - xv.z; op[4*gg + 2] = xv.z + e; lsum += (double)(e * e);
            e = q4.w - xv.w; op[4*gg + 3] = xv.w + e; lsum += (double)(e * e);
        }
    }

    s_red[tid] = lsum;
    __syncthreads();
    for (int s = TPB / 2; s > 0; s >>= 1) {
        if (tid < s) s_red[tid] += s_red[tid + s];
        __syncthreads();
    }
    if (tid == 0) g_partial[blockIdx.x] = s_red[0];
}

// ---------------------------------------------------------------------------
__global__ void vq_finalize(float* __restrict__ out) {
    __shared__ double sd[512];
    __shared__ float  sf[512];
    const int t = threadIdx.x;  // 512 threads

    double v = 0.0;
    for (int i = t; i < NBLOCKS; i += 512) v += g_partial[i];
    sd[t] = v;

    float c = (float)g_counts[t] / (float)NROWS;
    sf[t] = c * logf(c + 1e-10f);
    __syncthreads();

    for (int s = 256; s > 0; s >>= 1) {
        if (t < s) { sd[t] += sd[t + s]; sf[t] += sf[t + s]; }
        __syncthreads();
    }
    if (t == 0) {
        float m = (float)(sd[0] / ((double)NROWS * (double)DIM));
        out[0] = m + 0.25f * m;
        out[1 + (size_t)NROWS * DIM] = expf(-sf[0]) / (float)KCODES;
    }
}

// ---------------------------------------------------------------------------
extern "C" void kernel_launch(void* const* d_in, const int* in_sizes, int n_in,
                              void* d_out, int out_size) {
    const float* X = (const float*)d_in[0];   // inputs  [N, 64]
    const float* W = (const float*)d_in[1];   // emb_weight [512, 64]
    float* out = (float*)d_out;

    cudaFuncSetAttribute((const void*)vq_main,
                         cudaFuncAttributeMaxDynamicSharedMemorySize, DYN_SMEM);

    vq_prep<<<KCODES / 64, 64>>>(W);
    vq_main<<<NBLOCKS, TPB, DYN_SMEM>>>(X, W, out);
    vq_finalize<<<1, KCODES>>>(out);
}